// round 16
// baseline (speedup 1.0000x reference)
#include <cuda_runtime.h>

#define NFFT 16000
#define NH   8000
#define BT   896
#define NTASK 800
// 16000-domain padding (forward stages)
#define PHI(i)  ((i) + 6 * ((i) / 100))
#define SMPAD   (NFFT + 6 * (NFFT / 100))        // 16960 float2
// 8000-domain padding (inverse stages), separate region
#define PHI8(i) ((i) + 3 * ((i) / 50))
#define SMPAD8  (NH + 3 * (NH / 50))             // 8480 float2
#define SMTOTAL ((SMPAD + SMPAD8) * sizeof(float2))  // 203,520 B

// Forward plan (DIF) on 16000: 16,10,10,10 -> strides 1000,100,10,1
// Inverse plan (DIT) on 8000:  [16,10,10,5]; digit maps as in earlier rounds.

__device__ __align__(16) float2 g_tw[NFFT];      // e^{-2*pi*i*t/16000}
__device__ __align__(16) float2 g_twf1000[100];  // g_tw[16*n2]
__device__ __align__(16) float2 g_twf100[16];    // g_tw[160*n2]
__device__ __align__(16) float2 g_twi50[8];      // conj g_tw[320*n2]
__device__ __align__(16) float2 g_twi500[56];    // conj g_tw[32*n2]
__device__ __align__(16) float2 g_twi8000[500];  // conj g_tw[2*n2]

// Flat init: ONE sincospif per thread (fp32, pi-exact scaling) — keeps the
// init kernel ~1us inside the timed graph (the fp64 version cost ~12us).
#define N_INIT (NFFT + 100 + 10 + 5 + 50 + 500)

__global__ void init_tables_kernel() {
    int p = blockIdx.x * blockDim.x + threadIdx.x;
    float s, c;
    if (p < NFFT) {
        sincospif(-(float)p / 8000.0f, &s, &c);
        g_tw[p] = make_float2(c, s);
        return;
    }
    int q = p - NFFT;
    if (q < 100) {                       // g_twf1000[q] = cis(-pi*q/500)
        sincospif(-(float)q / 500.0f, &s, &c);
        g_twf1000[q] = make_float2(c, s);
        return;
    }
    q -= 100;
    if (q < 10) {                        // g_twf100[q] = cis(-pi*q/50)
        sincospif(-(float)q / 50.0f, &s, &c);
        g_twf100[q] = make_float2(c, s);
        return;
    }
    q -= 10;
    if (q < 5) {                         // g_twi50[q] = cis(+pi*q/25)
        sincospif((float)q / 25.0f, &s, &c);
        g_twi50[q] = make_float2(c, s);
        return;
    }
    q -= 5;
    if (q < 50) {                        // g_twi500[q] = cis(+pi*q/250)
        sincospif((float)q / 250.0f, &s, &c);
        g_twi500[q] = make_float2(c, s);
        return;
    }
    q -= 50;
    if (q < 500) {                       // g_twi8000[q] = cis(+pi*q/4000)
        sincospif((float)q / 4000.0f, &s, &c);
        g_twi8000[q] = make_float2(c, s);
    }
}

__device__ __forceinline__ int block_of(int f0) {
    return 100 * (f0 & 15) + 10 * ((f0 >> 4) % 10) + (f0 / 160);
}

__device__ __forceinline__ float2 cadd(float2 a, float2 b) { return make_float2(a.x + b.x, a.y + b.y); }
__device__ __forceinline__ float2 csub(float2 a, float2 b) { return make_float2(a.x - b.x, a.y - b.y); }
__device__ __forceinline__ float2 cmul(float2 a, float2 b) {
    return make_float2(fmaf(a.x, b.x, -a.y * b.y), fmaf(a.x, b.y, a.y * b.x));
}
__device__ __forceinline__ float2 cmulc(float2 a, float cr, float ci) {
    return make_float2(fmaf(a.x, cr, -a.y * ci), fmaf(a.x, ci, a.y * cr));
}
template <int DIR>
__device__ __forceinline__ float2 cmuli(float2 a) {   // * (DIR*i)
    return (DIR > 0) ? make_float2(-a.y, a.x) : make_float2(a.y, -a.x);
}

template <int DIR>
__device__ __forceinline__ void dft4(float2* x) {
    float2 t0 = cadd(x[0], x[2]);
    float2 t1 = csub(x[0], x[2]);
    float2 t2 = cadd(x[1], x[3]);
    float2 t3 = cmuli<DIR>(csub(x[1], x[3]));
    x[0] = cadd(t0, t2);
    x[2] = csub(t0, t2);
    x[1] = cadd(t1, t3);
    x[3] = csub(t1, t3);
}

template <int DIR>
__device__ __forceinline__ void dft5(float2* x) {
    const float c1 = 0.30901699437494742f;
    const float c2 = -0.80901699437494745f;
    const float s1 = 0.95105651629515357f;
    const float s2 = 0.58778525229247313f;
    float2 t1 = cadd(x[1], x[4]);
    float2 t2 = cadd(x[2], x[3]);
    float2 t3 = csub(x[1], x[4]);
    float2 t4 = csub(x[2], x[3]);
    float2 x0 = x[0];
    float2 a1 = make_float2(x0.x + c1 * t1.x + c2 * t2.x, x0.y + c1 * t1.y + c2 * t2.y);
    float2 a2 = make_float2(x0.x + c2 * t1.x + c1 * t2.x, x0.y + c2 * t1.y + c1 * t2.y);
    float2 b1 = make_float2(s1 * t3.x + s2 * t4.x, s1 * t3.y + s2 * t4.y);
    float2 b2 = make_float2(s2 * t3.x - s1 * t4.x, s2 * t3.y - s1 * t4.y);
    x[0] = make_float2(x0.x + t1.x + t2.x, x0.y + t1.y + t2.y);
    float2 ib1 = cmuli<DIR>(b1);
    float2 ib2 = cmuli<DIR>(b2);
    x[1] = cadd(a1, ib1);
    x[4] = csub(a1, ib1);
    x[2] = cadd(a2, ib2);
    x[3] = csub(a2, ib2);
}

// 10-point DFT = 2x5 CT, stride-S register access.
template <int DIR, int S>
__device__ __forceinline__ void dft10s(float2* x) {
    const float C36 = 0.80901699437494742f;
    const float S36 = 0.58778525229247313f;
    const float C72 = 0.30901699437494742f;
    const float S72 = 0.95105651629515357f;
    const float D = (float)DIR;
    float2 a[5], c[5];
#pragma unroll
    for (int k = 0; k < 5; k++) {
        a[k] = cadd(x[k * S], x[(k + 5) * S]);
        c[k] = csub(x[k * S], x[(k + 5) * S]);
    }
    c[1] = cmulc(c[1], C36, D * S36);
    c[2] = cmulc(c[2], C72, D * S72);
    c[3] = cmulc(c[3], -C72, D * S72);
    c[4] = cmulc(c[4], -C36, D * S36);
    dft5<DIR>(a);
    dft5<DIR>(c);
    x[0 * S] = a[0]; x[2 * S] = a[1]; x[4 * S] = a[2]; x[6 * S] = a[3]; x[8 * S] = a[4];
    x[1 * S] = c[0]; x[3 * S] = c[1]; x[5 * S] = c[2]; x[7 * S] = c[3]; x[9 * S] = c[4];
}

// 16-point DFT = 4x4 CT, stride-S register access.
template <int DIR, int S>
__device__ __forceinline__ void dft16s(float2* x) {
    const float C1 = 0.92387953251128674f;
    const float S1 = 0.38268343236508978f;
    const float C2 = 0.70710678118654752f;
    const float D = (float)DIR;
    float2 y[16];
#pragma unroll
    for (int n2 = 0; n2 < 4; n2++) {
        float2 t[4] = {x[n2 * S], x[(n2 + 4) * S], x[(n2 + 8) * S], x[(n2 + 12) * S]};
        dft4<DIR>(t);
        if (n2 == 1) {
            t[1] = cmulc(t[1], C1, D * S1);
            t[2] = cmulc(t[2], C2, D * C2);
            t[3] = cmulc(t[3], S1, D * C1);
        } else if (n2 == 2) {
            t[1] = cmulc(t[1], C2, D * C2);
            t[2] = cmuli<DIR>(t[2]);
            t[3] = cmulc(t[3], -C2, D * C2);
        } else if (n2 == 3) {
            t[1] = cmulc(t[1], S1, D * C1);
            t[2] = cmulc(t[2], -C2, D * C2);
            t[3] = cmulc(t[3], -C1, -D * S1);
        }
        y[0 + n2] = t[0]; y[4 + n2] = t[1]; y[8 + n2] = t[2]; y[12 + n2] = t[3];
    }
#pragma unroll
    for (int k1 = 0; k1 < 4; k1++) {
        float2 t[4] = {y[k1 * 4 + 0], y[k1 * 4 + 1], y[k1 * 4 + 2], y[k1 * 4 + 3]};
        dft4<DIR>(t);
        x[(k1 + 0) * S] = t[0]; x[(k1 + 4) * S] = t[1];
        x[(k1 + 8) * S] = t[2]; x[(k1 + 12) * S] = t[3];
    }
}

// Twiddle application: odd/even accumulator chains stepping by w^2.
template <int S>
__device__ __forceinline__ void apply_tw10_chain(float2* x, float2 w1) {
    float2 w2 = cmul(w1, w1);
    float2 wo = w1, we = w2;
    x[1 * S] = cmul(x[1 * S], wo);
    x[2 * S] = cmul(x[2 * S], we);
#pragma unroll
    for (int j = 3; j < 10; j += 2) {
        wo = cmul(wo, w2); x[j * S] = cmul(x[j * S], wo);
        if (j + 1 < 10) { we = cmul(we, w2); x[(j + 1) * S] = cmul(x[(j + 1) * S], we); }
    }
}

template <int S>
__device__ __forceinline__ void apply_tw16_chain(float2* x, float2 w1) {
    float2 w2 = cmul(w1, w1);
    float2 wo = w1, we = w2;
    x[1 * S] = cmul(x[1 * S], wo);
    x[2 * S] = cmul(x[2 * S], we);
#pragma unroll
    for (int j = 3; j < 16; j += 2) {
        wo = cmul(wo, w2); x[j * S] = cmul(x[j * S], wo);
        if (j + 1 < 16) { we = cmul(we, w2); x[(j + 1) * S] = cmul(x[(j + 1) * S], we); }
    }
}

// Forward radix-16 stage (NS=16000, m=1000), DIF, paired via float4.
// Twiddle pair LDG issued BEFORE the smem loads so its latency overlaps the DFTs.
__device__ __forceinline__ void stage16_fwd(float2* sm, int tid) {
    if (tid >= 500) return;
    int n2 = 2 * tid;
    float4 wv = *(const float4*)&g_tw[n2];   // prefetch (global, coalesced)
    float2 X[32];   // even slots: butterfly A (n2), odd: butterfly B (n2+1)
#pragma unroll
    for (int j = 0; j < 16; j++) {
        float4 t = *(const float4*)&sm[PHI(n2 + j * 1000)];
        X[2 * j]     = make_float2(t.x, t.y);
        X[2 * j + 1] = make_float2(t.z, t.w);
    }
    dft16s<-1, 2>(X);
    dft16s<-1, 2>(X + 1);
    apply_tw16_chain<2>(X, make_float2(wv.x, wv.y));
    apply_tw16_chain<2>(X + 1, make_float2(wv.z, wv.w));
#pragma unroll
    for (int j = 0; j < 16; j++) {
        *(float4*)&sm[PHI(n2 + j * 1000)] =
            make_float4(X[2 * j].x, X[2 * j].y, X[2 * j + 1].x, X[2 * j + 1].y);
    }
}

// Forward radix-10 stage, two adjacent butterflies per thread; 800 tasks.
template <int NS>
__device__ __forceinline__ void stage10_paired(float2* sm, int tid, const float2* __restrict__ tab) {
    constexpr int m = NS / 10;
    constexpr int halfm = m / 2;
    if (tid >= NTASK) return;
    int blk = tid / halfm;
    int h = tid - blk * halfm;
    int n2 = 2 * h;
    int base = blk * NS + n2;
    float4 wv = *(const float4*)&tab[n2];    // prefetch
    float2 X[20];
#pragma unroll
    for (int j = 0; j < 10; j++) {
        float4 t = *(const float4*)&sm[PHI(base + j * m)];
        X[2 * j]     = make_float2(t.x, t.y);
        X[2 * j + 1] = make_float2(t.z, t.w);
    }
    dft10s<-1, 2>(X);
    apply_tw10_chain<2>(X, make_float2(wv.x, wv.y));
    dft10s<-1, 2>(X + 1);
    apply_tw10_chain<2>(X + 1, make_float2(wv.z, wv.w));
#pragma unroll
    for (int j = 0; j < 10; j++) {
        *(float4*)&sm[PHI(base + j * m)] =
            make_float4(X[2 * j].x, X[2 * j].y, X[2 * j + 1].x, X[2 * j + 1].y);
    }
}

// Inverse (DIT) stage on the 8000-point array; w1 from pre-conjugated coalesced table.
template <int R, int NS, bool TO_GMEM>
__device__ __forceinline__ void stage8_inv(float2* s8, int tid, float2* __restrict__ gout2,
                                           const float2* __restrict__ tab) {
    constexpr int m = NS / R;
    constexpr int nb = NH / R;
    for (int u = tid; u < nb; u += BT) {
        int blk = u / m;
        int n2 = u - blk * m;
        int base = blk * NS + n2;
        float2 w1 = tab[n2];                 // prefetch before smem loads
        float2 x[R];
#pragma unroll
        for (int j = 0; j < R; j++) x[j] = s8[PHI8(base + j * m)];
        if constexpr (R == 16) {
            apply_tw16_chain<1>(x, w1);
            dft16s<1, 1>(x);
        } else {
            apply_tw10_chain<1>(x, w1);
            dft10s<1, 1>(x);
        }
#pragma unroll
        for (int j = 0; j < R; j++) {
            if constexpr (TO_GMEM) gout2[base + j * m] = x[j];   // c[n] -> (z[2n], z[2n+1])
            else s8[PHI8(base + j * m)] = x[j];
        }
    }
}

__device__ __forceinline__ void pw(float2& A, float2& C, float scale) {
    float2 a = A, c = C;
    float2 Fi = make_float2(a.x + c.x, a.y - c.y);
    float2 Fs = make_float2(a.y + c.y, -(a.x - c.x));
    float2 Z = cmul(Fi, Fs);
    Z.x *= scale; Z.y *= scale;
    A = Z;
    C = make_float2(Z.x, -Z.y);
}

// Pack Z-block (10 values, f = f0+1600t) into 5 C values of the 8000-domain,
// then first inverse stage (radix-5), store at s8[PHI8(5b + j)].
__device__ __forceinline__ void pack_inv5_store(const float2* x, float2 w0,
                                                float2* s8, int b) {
    const float RC[5] = {1.f, 0.80901699437494742f, 0.30901699437494742f,
                         -0.30901699437494742f, -0.80901699437494742f};
    const float RS[5] = {0.f, 0.58778525229247313f, 0.95105651629515357f,
                         0.95105651629515357f, 0.58778525229247313f};
    float2 C[5];
#pragma unroll
    for (int t = 0; t < 5; t++) {
        float2 S = cadd(x[t], x[t + 5]);
        float2 Dd = csub(x[t], x[t + 5]);
        float2 wt = (t == 0) ? w0 : cmul(w0, make_float2(RC[t], RS[t]));
        C[t] = cadd(S, cmuli<1>(cmul(wt, Dd)));
    }
    dft5<1>(C);
    int base = PHI8(5 * b);   // 5b..5b+4 never cross a 50-group
#pragma unroll
    for (int j = 0; j < 5; j++) s8[base + j] = C[j];
}

// Fused middle: forward radix-10 (m=1) + Hermitian pointwise + pack + inverse radix-5.
__device__ __forceinline__ void fused_mid(float2* sm, float2* s8, int tid) {
    if (tid >= NTASK) return;
    const float scale = 0.25f / (float)NFFT;
    int fa, fb;
    if (tid < 799) { fa = tid + 1; fb = 1600 - fa; }
    else           { fa = 0;       fb = 800; }
    int b  = block_of(fa);
    int b2 = block_of(fb);
    int pa = PHI(10 * b);
    int pb = PHI(10 * b2);
    float2 ta = g_tw[fa]; ta.y = -ta.y;   // prefetch; e^{+2pi i fa/16000}
    float2 tb = g_tw[fb]; tb.y = -tb.y;
    float2 xa[10], xb[10];
#pragma unroll
    for (int k = 0; k < 5; k++) {
        float4 t = *(const float4*)&sm[pa + 2 * k];
        xa[2 * k] = make_float2(t.x, t.y); xa[2 * k + 1] = make_float2(t.z, t.w);
        float4 s = *(const float4*)&sm[pb + 2 * k];
        xb[2 * k] = make_float2(s.x, s.y); xb[2 * k + 1] = make_float2(s.z, s.w);
    }
    dft10s<-1, 1>(xa);
    dft10s<-1, 1>(xb);
    if (tid < 799) {
#pragma unroll
        for (int t = 0; t < 10; t++) pw(xa[t], xb[9 - t], scale);
    } else {
        pw(xa[0], xa[0], scale);
        pw(xa[5], xa[5], scale);
        pw(xa[1], xa[9], scale);
        pw(xa[2], xa[8], scale);
        pw(xa[3], xa[7], scale);
        pw(xa[4], xa[6], scale);
        pw(xb[0], xb[9], scale);
        pw(xb[1], xb[8], scale);
        pw(xb[2], xb[7], scale);
        pw(xb[3], xb[6], scale);
        pw(xb[4], xb[5], scale);
    }
    pack_inv5_store(xa, ta, s8, b);
    pack_inv5_store(xb, tb, s8, b2);
}

__global__ void __launch_bounds__(BT, 1) mcb_main_kernel(
    const float* __restrict__ img, const float* __restrict__ seq,
    const int* __restrict__ hv, const float* __restrict__ sv,
    float* __restrict__ out, int d) {
    extern __shared__ float2 sm[];
    float2* s8 = sm + SMPAD;
    const int b = blockIdx.x;
    const int tid = threadIdx.x;

    float4* sm4 = (float4*)sm;
#pragma unroll 2
    for (int i = tid; i < SMPAD / 2; i += BT) sm4[i] = make_float4(0.f, 0.f, 0.f, 0.f);
    __syncthreads();

    // vectorized scatter: FOUR features per iteration (int4/float4 loads;
    // row bases are 16B-aligned: row stride = d floats, d % 4 == 0).
    {
        const int Q = d >> 2;   // feature quads (512 for d=2048 -> single pass)
        const int4*   hv4 = (const int4*)hv;
        const float4* sv4 = (const float4*)sv;
        const float4* im4 = (const float4*)(img + (size_t)b * d);
        const float4* sq4 = (const float4*)(seq + (size_t)b * d);
        for (int i = tid; i < Q; i += BT) {
            int4   h4 = hv4[i];
            float4 s4 = sv4[i];
            float4 a4 = im4[i];
            float4 q4 = sq4[i];
            int h0 = PHI(h4.x), h1 = PHI(h4.y), h2 = PHI(h4.z), h3 = PHI(h4.w);
            atomicAdd(&sm[h0].x, a4.x * s4.x);
            atomicAdd(&sm[h0].y, q4.x * s4.x);
            atomicAdd(&sm[h1].x, a4.y * s4.y);
            atomicAdd(&sm[h1].y, q4.y * s4.y);
            atomicAdd(&sm[h2].x, a4.z * s4.z);
            atomicAdd(&sm[h2].y, q4.z * s4.z);
            atomicAdd(&sm[h3].x, a4.w * s4.w);
            atomicAdd(&sm[h3].y, q4.w * s4.w);
        }
    }
    __syncthreads();

    float2* orow2 = (float2*)(out + (size_t)b * NFFT);

    // forward 16000: 16 (paired), 10, 10 | fused(10 + pointwise + pack + inv5)
    stage16_fwd(sm, tid);                        __syncthreads();
    stage10_paired<1000>(sm, tid, g_twf1000);    __syncthreads();
    stage10_paired<100>(sm, tid, g_twf100);      __syncthreads();
    fused_mid(sm, s8, tid);                      __syncthreads();
    // inverse 8000: 10 (m=5), 10 (m=50), 16 (m=500) -> gmem float2
    stage8_inv<10, 50, false>(s8, tid, orow2, g_twi50);     __syncthreads();
    stage8_inv<10, 500, false>(s8, tid, orow2, g_twi500);   __syncthreads();
    stage8_inv<16, 8000, true>(s8, tid, orow2, g_twi8000);
}

extern "C" void kernel_launch(void* const* d_in, const int* in_sizes, int n_in,
                              void* d_out, int out_size) {
    const float* img = (const float*)d_in[0];
    const float* seq = (const float*)d_in[1];
    const int* hv = (const int*)d_in[2];
    const float* sv = (const float*)d_in[3];
    float* out = (float*)d_out;

    int d = in_sizes[2];
    int B = in_sizes[0] / d;

    static_assert(NFFT == 16000 && NH == 8000, "plan assumes N=16000");

    cudaFuncSetAttribute(mcb_main_kernel, cudaFuncAttributeMaxDynamicSharedMemorySize,
                         SMTOTAL);

    init_tables_kernel<<<(N_INIT + 255) / 256, 256>>>();
    mcb_main_kernel<<<B, BT, SMTOTAL>>>(img, seq, hv, sv, out, d);
}

// round 17
// speedup vs baseline: 1.6213x; 1.6213x over previous
#include <cuda_runtime.h>

#define NFFT 16000
#define NH   8000
#define BT   800
// 16000-domain padding (forward stages)
#define PHI(i)  ((i) + 6 * ((i) / 100))
#define SMPAD   (NFFT + 6 * (NFFT / 100))        // 16960 float2
// 8000-domain padding (inverse stages), separate region
#define PHI8(i) ((i) + 3 * ((i) / 50))
#define SMPAD8  (NH + 3 * (NH / 50))             // 8480 float2
#define SMTOTAL ((SMPAD + SMPAD8) * sizeof(float2))  // 203,520 B

// Forward plan (DIF) on 16000: 16,10,10,10 -> strides 1000,100,10,1
// Inverse plan (DIT) on 8000:  [16,10,10,5]; digit maps as in earlier rounds.
// NOTE: BT=800 is load-bearing — the register cap is floor(65536/800)=81 and the
// kernel needs ~72-76; raising BT to 896 (cap 72) causes spills and a 1.6x slowdown.

__device__ __align__(16) float2 g_tw[NFFT];      // e^{-2*pi*i*t/16000}
__device__ __align__(16) float2 g_twf1000[100];  // g_tw[16*n2]
__device__ __align__(16) float2 g_twf100[16];    // g_tw[160*n2]
__device__ __align__(16) float2 g_twi50[8];      // conj g_tw[320*n2]
__device__ __align__(16) float2 g_twi500[56];    // conj g_tw[32*n2]
__device__ __align__(16) float2 g_twi8000[500];  // conj g_tw[2*n2]

// Flat init: ONE sincospif per thread (fp32, pi-exact scaling) — keeps the
// init kernel ~1us inside the timed graph (the fp64 version cost ~12us).
#define N_INIT (NFFT + 100 + 10 + 5 + 50 + 500)

__global__ void init_tables_kernel() {
    int p = blockIdx.x * blockDim.x + threadIdx.x;
    float s, c;
    if (p < NFFT) {
        sincospif(-(float)p / 8000.0f, &s, &c);
        g_tw[p] = make_float2(c, s);
        return;
    }
    int q = p - NFFT;
    if (q < 100) {                       // g_twf1000[q] = cis(-pi*q/500)
        sincospif(-(float)q / 500.0f, &s, &c);
        g_twf1000[q] = make_float2(c, s);
        return;
    }
    q -= 100;
    if (q < 10) {                        // g_twf100[q] = cis(-pi*q/50)
        sincospif(-(float)q / 50.0f, &s, &c);
        g_twf100[q] = make_float2(c, s);
        return;
    }
    q -= 10;
    if (q < 5) {                         // g_twi50[q] = cis(+pi*q/25)
        sincospif((float)q / 25.0f, &s, &c);
        g_twi50[q] = make_float2(c, s);
        return;
    }
    q -= 5;
    if (q < 50) {                        // g_twi500[q] = cis(+pi*q/250)
        sincospif((float)q / 250.0f, &s, &c);
        g_twi500[q] = make_float2(c, s);
        return;
    }
    q -= 50;
    if (q < 500) {                       // g_twi8000[q] = cis(+pi*q/4000)
        sincospif((float)q / 4000.0f, &s, &c);
        g_twi8000[q] = make_float2(c, s);
    }
}

__device__ __forceinline__ int block_of(int f0) {
    return 100 * (f0 & 15) + 10 * ((f0 >> 4) % 10) + (f0 / 160);
}

__device__ __forceinline__ float2 cadd(float2 a, float2 b) { return make_float2(a.x + b.x, a.y + b.y); }
__device__ __forceinline__ float2 csub(float2 a, float2 b) { return make_float2(a.x - b.x, a.y - b.y); }
__device__ __forceinline__ float2 cmul(float2 a, float2 b) {
    return make_float2(fmaf(a.x, b.x, -a.y * b.y), fmaf(a.x, b.y, a.y * b.x));
}
__device__ __forceinline__ float2 cmulc(float2 a, float cr, float ci) {
    return make_float2(fmaf(a.x, cr, -a.y * ci), fmaf(a.x, ci, a.y * cr));
}
template <int DIR>
__device__ __forceinline__ float2 cmuli(float2 a) {   // * (DIR*i)
    return (DIR > 0) ? make_float2(-a.y, a.x) : make_float2(a.y, -a.x);
}

template <int DIR>
__device__ __forceinline__ void dft4(float2* x) {
    float2 t0 = cadd(x[0], x[2]);
    float2 t1 = csub(x[0], x[2]);
    float2 t2 = cadd(x[1], x[3]);
    float2 t3 = cmuli<DIR>(csub(x[1], x[3]));
    x[0] = cadd(t0, t2);
    x[2] = csub(t0, t2);
    x[1] = cadd(t1, t3);
    x[3] = csub(t1, t3);
}

template <int DIR>
__device__ __forceinline__ void dft5(float2* x) {
    const float c1 = 0.30901699437494742f;
    const float c2 = -0.80901699437494745f;
    const float s1 = 0.95105651629515357f;
    const float s2 = 0.58778525229247313f;
    float2 t1 = cadd(x[1], x[4]);
    float2 t2 = cadd(x[2], x[3]);
    float2 t3 = csub(x[1], x[4]);
    float2 t4 = csub(x[2], x[3]);
    float2 x0 = x[0];
    float2 a1 = make_float2(x0.x + c1 * t1.x + c2 * t2.x, x0.y + c1 * t1.y + c2 * t2.y);
    float2 a2 = make_float2(x0.x + c2 * t1.x + c1 * t2.x, x0.y + c2 * t1.y + c1 * t2.y);
    float2 b1 = make_float2(s1 * t3.x + s2 * t4.x, s1 * t3.y + s2 * t4.y);
    float2 b2 = make_float2(s2 * t3.x - s1 * t4.x, s2 * t3.y - s1 * t4.y);
    x[0] = make_float2(x0.x + t1.x + t2.x, x0.y + t1.y + t2.y);
    float2 ib1 = cmuli<DIR>(b1);
    float2 ib2 = cmuli<DIR>(b2);
    x[1] = cadd(a1, ib1);
    x[4] = csub(a1, ib1);
    x[2] = cadd(a2, ib2);
    x[3] = csub(a2, ib2);
}

// 10-point DFT = 2x5 CT, stride-S register access.
template <int DIR, int S>
__device__ __forceinline__ void dft10s(float2* x) {
    const float C36 = 0.80901699437494742f;
    const float S36 = 0.58778525229247313f;
    const float C72 = 0.30901699437494742f;
    const float S72 = 0.95105651629515357f;
    const float D = (float)DIR;
    float2 a[5], c[5];
#pragma unroll
    for (int k = 0; k < 5; k++) {
        a[k] = cadd(x[k * S], x[(k + 5) * S]);
        c[k] = csub(x[k * S], x[(k + 5) * S]);
    }
    c[1] = cmulc(c[1], C36, D * S36);
    c[2] = cmulc(c[2], C72, D * S72);
    c[3] = cmulc(c[3], -C72, D * S72);
    c[4] = cmulc(c[4], -C36, D * S36);
    dft5<DIR>(a);
    dft5<DIR>(c);
    x[0 * S] = a[0]; x[2 * S] = a[1]; x[4 * S] = a[2]; x[6 * S] = a[3]; x[8 * S] = a[4];
    x[1 * S] = c[0]; x[3 * S] = c[1]; x[5 * S] = c[2]; x[7 * S] = c[3]; x[9 * S] = c[4];
}

// 16-point DFT = 4x4 CT, stride-S register access.
template <int DIR, int S>
__device__ __forceinline__ void dft16s(float2* x) {
    const float C1 = 0.92387953251128674f;
    const float S1 = 0.38268343236508978f;
    const float C2 = 0.70710678118654752f;
    const float D = (float)DIR;
    float2 y[16];
#pragma unroll
    for (int n2 = 0; n2 < 4; n2++) {
        float2 t[4] = {x[n2 * S], x[(n2 + 4) * S], x[(n2 + 8) * S], x[(n2 + 12) * S]};
        dft4<DIR>(t);
        if (n2 == 1) {
            t[1] = cmulc(t[1], C1, D * S1);
            t[2] = cmulc(t[2], C2, D * C2);
            t[3] = cmulc(t[3], S1, D * C1);
        } else if (n2 == 2) {
            t[1] = cmulc(t[1], C2, D * C2);
            t[2] = cmuli<DIR>(t[2]);
            t[3] = cmulc(t[3], -C2, D * C2);
        } else if (n2 == 3) {
            t[1] = cmulc(t[1], S1, D * C1);
            t[2] = cmulc(t[2], -C2, D * C2);
            t[3] = cmulc(t[3], -C1, -D * S1);
        }
        y[0 + n2] = t[0]; y[4 + n2] = t[1]; y[8 + n2] = t[2]; y[12 + n2] = t[3];
    }
#pragma unroll
    for (int k1 = 0; k1 < 4; k1++) {
        float2 t[4] = {y[k1 * 4 + 0], y[k1 * 4 + 1], y[k1 * 4 + 2], y[k1 * 4 + 3]};
        dft4<DIR>(t);
        x[(k1 + 0) * S] = t[0]; x[(k1 + 4) * S] = t[1];
        x[(k1 + 8) * S] = t[2]; x[(k1 + 12) * S] = t[3];
    }
}

// Twiddle application: odd/even accumulator chains stepping by w^2.
template <int S>
__device__ __forceinline__ void apply_tw10_chain(float2* x, float2 w1) {
    float2 w2 = cmul(w1, w1);
    float2 wo = w1, we = w2;
    x[1 * S] = cmul(x[1 * S], wo);
    x[2 * S] = cmul(x[2 * S], we);
#pragma unroll
    for (int j = 3; j < 10; j += 2) {
        wo = cmul(wo, w2); x[j * S] = cmul(x[j * S], wo);
        if (j + 1 < 10) { we = cmul(we, w2); x[(j + 1) * S] = cmul(x[(j + 1) * S], we); }
    }
}

template <int S>
__device__ __forceinline__ void apply_tw16_chain(float2* x, float2 w1) {
    float2 w2 = cmul(w1, w1);
    float2 wo = w1, we = w2;
    x[1 * S] = cmul(x[1 * S], wo);
    x[2 * S] = cmul(x[2 * S], we);
#pragma unroll
    for (int j = 3; j < 16; j += 2) {
        wo = cmul(wo, w2); x[j * S] = cmul(x[j * S], wo);
        if (j + 1 < 16) { we = cmul(we, w2); x[(j + 1) * S] = cmul(x[(j + 1) * S], we); }
    }
}

// Forward radix-16 stage (NS=16000, m=1000), DIF, paired via float4.
// Twiddle pair LDG issued BEFORE the smem loads so its latency overlaps the DFTs.
__device__ __forceinline__ void stage16_fwd(float2* sm, int tid) {
    if (tid >= 500) return;
    int n2 = 2 * tid;
    float4 wv = *(const float4*)&g_tw[n2];   // prefetch (global, coalesced)
    float2 X[32];   // even slots: butterfly A (n2), odd: butterfly B (n2+1)
#pragma unroll
    for (int j = 0; j < 16; j++) {
        float4 t = *(const float4*)&sm[PHI(n2 + j * 1000)];
        X[2 * j]     = make_float2(t.x, t.y);
        X[2 * j + 1] = make_float2(t.z, t.w);
    }
    dft16s<-1, 2>(X);
    dft16s<-1, 2>(X + 1);
    apply_tw16_chain<2>(X, make_float2(wv.x, wv.y));
    apply_tw16_chain<2>(X + 1, make_float2(wv.z, wv.w));
#pragma unroll
    for (int j = 0; j < 16; j++) {
        *(float4*)&sm[PHI(n2 + j * 1000)] =
            make_float4(X[2 * j].x, X[2 * j].y, X[2 * j + 1].x, X[2 * j + 1].y);
    }
}

// Forward radix-10 stage, two adjacent butterflies per thread; 800 tasks = BT.
template <int NS>
__device__ __forceinline__ void stage10_paired(float2* sm, int tid, const float2* __restrict__ tab) {
    constexpr int m = NS / 10;
    constexpr int halfm = m / 2;
    int blk = tid / halfm;
    int h = tid - blk * halfm;
    int n2 = 2 * h;
    int base = blk * NS + n2;
    float4 wv = *(const float4*)&tab[n2];    // prefetch
    float2 X[20];
#pragma unroll
    for (int j = 0; j < 10; j++) {
        float4 t = *(const float4*)&sm[PHI(base + j * m)];
        X[2 * j]     = make_float2(t.x, t.y);
        X[2 * j + 1] = make_float2(t.z, t.w);
    }
    dft10s<-1, 2>(X);
    apply_tw10_chain<2>(X, make_float2(wv.x, wv.y));
    dft10s<-1, 2>(X + 1);
    apply_tw10_chain<2>(X + 1, make_float2(wv.z, wv.w));
#pragma unroll
    for (int j = 0; j < 10; j++) {
        *(float4*)&sm[PHI(base + j * m)] =
            make_float4(X[2 * j].x, X[2 * j].y, X[2 * j + 1].x, X[2 * j + 1].y);
    }
}

// Inverse (DIT) stage on the 8000-point array; w1 from pre-conjugated coalesced table.
template <int R, int NS, bool TO_GMEM>
__device__ __forceinline__ void stage8_inv(float2* s8, int tid, float2* __restrict__ gout2,
                                           const float2* __restrict__ tab) {
    constexpr int m = NS / R;
    constexpr int nb = NH / R;
    for (int u = tid; u < nb; u += BT) {
        int blk = u / m;
        int n2 = u - blk * m;
        int base = blk * NS + n2;
        float2 w1 = tab[n2];                 // prefetch before smem loads
        float2 x[R];
#pragma unroll
        for (int j = 0; j < R; j++) x[j] = s8[PHI8(base + j * m)];
        if constexpr (R == 16) {
            apply_tw16_chain<1>(x, w1);
            dft16s<1, 1>(x);
        } else {
            apply_tw10_chain<1>(x, w1);
            dft10s<1, 1>(x);
        }
#pragma unroll
        for (int j = 0; j < R; j++) {
            if constexpr (TO_GMEM) gout2[base + j * m] = x[j];   // c[n] -> (z[2n], z[2n+1])
            else s8[PHI8(base + j * m)] = x[j];
        }
    }
}

__device__ __forceinline__ void pw(float2& A, float2& C, float scale) {
    float2 a = A, c = C;
    float2 Fi = make_float2(a.x + c.x, a.y - c.y);
    float2 Fs = make_float2(a.y + c.y, -(a.x - c.x));
    float2 Z = cmul(Fi, Fs);
    Z.x *= scale; Z.y *= scale;
    A = Z;
    C = make_float2(Z.x, -Z.y);
}

// Pack Z-block (10 values, f = f0+1600t) into 5 C values of the 8000-domain,
// then first inverse stage (radix-5), store at s8[PHI8(5b + j)].
__device__ __forceinline__ void pack_inv5_store(const float2* x, float2 w0,
                                                float2* s8, int b) {
    const float RC[5] = {1.f, 0.80901699437494742f, 0.30901699437494742f,
                         -0.30901699437494742f, -0.80901699437494742f};
    const float RS[5] = {0.f, 0.58778525229247313f, 0.95105651629515357f,
                         0.95105651629515357f, 0.58778525229247313f};
    float2 C[5];
#pragma unroll
    for (int t = 0; t < 5; t++) {
        float2 S = cadd(x[t], x[t + 5]);
        float2 Dd = csub(x[t], x[t + 5]);
        float2 wt = (t == 0) ? w0 : cmul(w0, make_float2(RC[t], RS[t]));
        C[t] = cadd(S, cmuli<1>(cmul(wt, Dd)));
    }
    dft5<1>(C);
    int base = PHI8(5 * b);   // 5b..5b+4 never cross a 50-group
#pragma unroll
    for (int j = 0; j < 5; j++) s8[base + j] = C[j];
}

// Fused middle: forward radix-10 (m=1) + Hermitian pointwise + pack + inverse radix-5.
__device__ __forceinline__ void fused_mid(float2* sm, float2* s8, int tid) {
    const float scale = 0.25f / (float)NFFT;
    int fa, fb;
    if (tid < 799) { fa = tid + 1; fb = 1600 - fa; }
    else           { fa = 0;       fb = 800; }
    int b  = block_of(fa);
    int b2 = block_of(fb);
    int pa = PHI(10 * b);
    int pb = PHI(10 * b2);
    float2 ta = g_tw[fa]; ta.y = -ta.y;   // prefetch; e^{+2pi i fa/16000}
    float2 tb = g_tw[fb]; tb.y = -tb.y;
    float2 xa[10], xb[10];
#pragma unroll
    for (int k = 0; k < 5; k++) {
        float4 t = *(const float4*)&sm[pa + 2 * k];
        xa[2 * k] = make_float2(t.x, t.y); xa[2 * k + 1] = make_float2(t.z, t.w);
        float4 s = *(const float4*)&sm[pb + 2 * k];
        xb[2 * k] = make_float2(s.x, s.y); xb[2 * k + 1] = make_float2(s.z, s.w);
    }
    dft10s<-1, 1>(xa);
    dft10s<-1, 1>(xb);
    if (tid < 799) {
#pragma unroll
        for (int t = 0; t < 10; t++) pw(xa[t], xb[9 - t], scale);
    } else {
        pw(xa[0], xa[0], scale);
        pw(xa[5], xa[5], scale);
        pw(xa[1], xa[9], scale);
        pw(xa[2], xa[8], scale);
        pw(xa[3], xa[7], scale);
        pw(xa[4], xa[6], scale);
        pw(xb[0], xb[9], scale);
        pw(xb[1], xb[8], scale);
        pw(xb[2], xb[7], scale);
        pw(xb[3], xb[6], scale);
        pw(xb[4], xb[5], scale);
    }
    pack_inv5_store(xa, ta, s8, b);
    pack_inv5_store(xb, tb, s8, b2);
}

__global__ void __launch_bounds__(BT) mcb_main_kernel(
    const float* __restrict__ img, const float* __restrict__ seq,
    const int* __restrict__ hv, const float* __restrict__ sv,
    float* __restrict__ out, int d) {
    extern __shared__ float2 sm[];
    float2* s8 = sm + SMPAD;
    const int b = blockIdx.x;
    const int tid = threadIdx.x;

    float4* sm4 = (float4*)sm;
    for (int i = tid; i < SMPAD / 2; i += BT) sm4[i] = make_float4(0.f, 0.f, 0.f, 0.f);
    __syncthreads();

    // vectorized scatter: FOUR features per iteration (int4/float4 loads;
    // row bases are 16B-aligned: row stride = d floats, d % 4 == 0).
    {
        const int Q = d >> 2;   // feature quads (512 for d=2048 -> single pass)
        const int4*   hv4 = (const int4*)hv;
        const float4* sv4 = (const float4*)sv;
        const float4* im4 = (const float4*)(img + (size_t)b * d);
        const float4* sq4 = (const float4*)(seq + (size_t)b * d);
        for (int i = tid; i < Q; i += BT) {
            int4   h4 = hv4[i];
            float4 s4 = sv4[i];
            float4 a4 = im4[i];
            float4 q4 = sq4[i];
            int h0 = PHI(h4.x), h1 = PHI(h4.y), h2 = PHI(h4.z), h3 = PHI(h4.w);
            atomicAdd(&sm[h0].x, a4.x * s4.x);
            atomicAdd(&sm[h0].y, q4.x * s4.x);
            atomicAdd(&sm[h1].x, a4.y * s4.y);
            atomicAdd(&sm[h1].y, q4.y * s4.y);
            atomicAdd(&sm[h2].x, a4.z * s4.z);
            atomicAdd(&sm[h2].y, q4.z * s4.z);
            atomicAdd(&sm[h3].x, a4.w * s4.w);
            atomicAdd(&sm[h3].y, q4.w * s4.w);
        }
    }
    __syncthreads();

    float2* orow2 = (float2*)(out + (size_t)b * NFFT);

    // forward 16000: 16 (paired), 10, 10 | fused(10 + pointwise + pack + inv5)
    stage16_fwd(sm, tid);                        __syncthreads();
    stage10_paired<1000>(sm, tid, g_twf1000);    __syncthreads();
    stage10_paired<100>(sm, tid, g_twf100);      __syncthreads();
    fused_mid(sm, s8, tid);                      __syncthreads();
    // inverse 8000: 10 (m=5), 10 (m=50), 16 (m=500) -> gmem float2
    stage8_inv<10, 50, false>(s8, tid, orow2, g_twi50);     __syncthreads();
    stage8_inv<10, 500, false>(s8, tid, orow2, g_twi500);   __syncthreads();
    stage8_inv<16, 8000, true>(s8, tid, orow2, g_twi8000);
}

extern "C" void kernel_launch(void* const* d_in, const int* in_sizes, int n_in,
                              void* d_out, int out_size) {
    const float* img = (const float*)d_in[0];
    const float* seq = (const float*)d_in[1];
    const int* hv = (const int*)d_in[2];
    const float* sv = (const float*)d_in[3];
    float* out = (float*)d_out;

    int d = in_sizes[2];
    int B = in_sizes[0] / d;

    static_assert(NFFT == 16000 && NH == 8000, "plan assumes N=16000");

    cudaFuncSetAttribute(mcb_main_kernel, cudaFuncAttributeMaxDynamicSharedMemorySize,
                         SMTOTAL);

    init_tables_kernel<<<(N_INIT + 255) / 256, 256>>>();
    mcb_main_kernel<<<B, BT, SMTOTAL>>>(img, seq, hv, sv, out, d);
}